// round 13
// baseline (speedup 1.0000x reference)
#include <cuda_runtime.h>
#include <math.h>
#include <stdint.h>

// Problem shape (fixed by the dataset)
#define NROWS   32768      // B*T = 4*8192
#define DDIM    1024
#define KD      6
#define NP      8
#define ROWS_PER_WARP 4
#define THREADS 256
#define WARPS_PER_BLOCK (THREADS/32)
#define ROWS_PER_CTA (ROWS_PER_WARP*WARPS_PER_BLOCK)          // 32
#define GRID    (NROWS / ROWS_PER_CTA)                        // 1024
#define CHUNK   128                                           // floats per row per stage
#define NCHUNKS (DDIM / CHUNK)                                // 8
#define NSTAGE  4                                             // per-warp ring depth
#define STAGE_FLOATS (ROWS_PER_WARP * CHUNK)                  // 512 floats = 2KB
#define WARP_BUF_FLOATS (NSTAGE * STAGE_FLOATS)               // 2048 floats = 8KB

// dynamic smem layout (floats): W[6144] | xbuf[8*2048] | p_s[64] | h[1]
#define SM_W    0
#define SM_XB   (KD * DDIM)
#define SM_PS   (SM_XB + WARPS_PER_BLOCK * WARP_BUF_FLOATS)
#define SM_H    (SM_PS + NP * 8)
#define SMEM_FLOATS (SM_H + 1)
#define SMEM_BYTES  (SMEM_FLOATS * 4)                         // ~90.4 KB

typedef unsigned long long u64;

// Packed dual-FMA (sm_103a FFMA2). acc.{lo,hi} += a.{lo,hi} * b.{lo,hi}
__device__ __forceinline__ void ffma2(u64& acc, u64 a, u64 b) {
    asm("fma.rn.f32x2 %0, %1, %2, %0;" : "+l"(acc) : "l"(a), "l"(b));
}
__device__ __forceinline__ float f32x2_sum(u64 v) {
    uint32_t lo, hi;
    asm("mov.b64 {%0, %1}, %2;" : "=r"(lo), "=r"(hi) : "l"(v));
    return __uint_as_float(lo) + __uint_as_float(hi);
}
// 16-byte async copy gmem -> smem (LDGSTS)
__device__ __forceinline__ void cp16(uint32_t saddr, const float* gaddr) {
    asm volatile("cp.async.cg.shared.global [%0], [%1], 16;" :: "r"(saddr), "l"(gaddr));
}
__device__ __forceinline__ void cp_commit() {
    asm volatile("cp.async.commit_group;");
}
template <int N>
__device__ __forceinline__ void cp_wait() {
    asm volatile("cp.async.wait_group %0;" :: "n"(N));
}

__global__ __launch_bounds__(THREADS, 2)
void q6_kernel(const float* __restrict__ x,
               const float* __restrict__ W,
               const float* __restrict__ protos,
               const float* __restrict__ hs,
               float* __restrict__ out)
{
    extern __shared__ float smem[];
    float* w_s = smem + SM_W;
    float* p_s = smem + SM_PS;

    const int tid  = threadIdx.x;
    const int warp = tid >> 5;
    const int lane = tid & 31;
    const int row0 = blockIdx.x * ROWS_PER_CTA + warp * ROWS_PER_WARP;

    // this warp's private ring buffer
    float* xb_warp = smem + SM_XB + warp * WARP_BUF_FLOATS;
    const uint32_t xb_sa = (uint32_t)__cvta_generic_to_shared(xb_warp)
                         + (uint32_t)lane * 16u;
    const float* xg = x + (size_t)row0 * DDIM + lane * 4;   // lane's 16B column

    // issue stage c of this warp's 4 rows (lane copies its own 16B per row)
    #define ISSUE(c) do {                                                    \
        const uint32_t dst = xb_sa + (uint32_t)(((c) & (NSTAGE-1)) * STAGE_FLOATS * 4); \
        const float* g = xg + (c) * CHUNK;                                   \
        cp16(dst + 0 * CHUNK * 4, g + 0 * DDIM);                             \
        cp16(dst + 1 * CHUNK * 4, g + 1 * DDIM);                             \
        cp16(dst + 2 * CHUNK * 4, g + 2 * DDIM);                             \
        cp16(dst + 3 * CHUNK * 4, g + 3 * DDIM);                             \
        cp_commit();                                                         \
    } while (0)

    // ---- prologue: get 3 stages in flight before anything else
    ISSUE(0); ISSUE(1); ISSUE(2);

    // ---- stage W into shared (coalesced float4 copy, overlaps with cp.async)
    {
        const float4* Wv  = reinterpret_cast<const float4*>(W);
        float4*       wsv = reinterpret_cast<float4*>(w_s);
        #pragma unroll
        for (int i = 0; i < (KD * DDIM / 4) / THREADS; ++i)
            wsv[tid + i * THREADS] = Wv[tid + i * THREADS];
    }
    // ---- normalize prototypes into shared
    if (tid < NP) {
        float pv[KD]; float ss = 0.f;
        #pragma unroll
        for (int k = 0; k < KD; ++k) { pv[k] = protos[tid * KD + k]; ss += pv[k] * pv[k]; }
        float inv = 1.f / fmaxf(sqrtf(ss), 1e-12f);
        #pragma unroll
        for (int k = 0; k < KD; ++k) p_s[tid * 8 + k] = pv[k] * inv;
    }
    if (tid == 0) smem[SM_H] = hs[0];
    __syncthreads();   // the ONLY CTA barrier: W + p_s visible before compute

    // ---- accumulators: 4 rows x 6 k, packed f32x2
    u64 s2[ROWS_PER_WARP][KD];
    #pragma unroll
    for (int r = 0; r < ROWS_PER_WARP; ++r)
        #pragma unroll
        for (int k = 0; k < KD; ++k) s2[r][k] = 0ULL;

    const ulonglong2* wv2 = reinterpret_cast<const ulonglong2*>(w_s);

    #define COMPUTE(c) do {                                                  \
        const ulonglong2* xs = reinterpret_cast<const ulonglong2*>(          \
            xb_warp + ((c) & (NSTAGE-1)) * STAGE_FLOATS);                    \
        const ulonglong2 a0 = xs[0 * 32 + lane];                             \
        const ulonglong2 a1 = xs[1 * 32 + lane];                             \
        const ulonglong2 a2 = xs[2 * 32 + lane];                             \
        const ulonglong2 a3 = xs[3 * 32 + lane];                             \
        _Pragma("unroll")                                                    \
        for (int k = 0; k < KD; ++k) {                                       \
            const ulonglong2 w2 = wv2[k * (DDIM / 4) + (c) * 32 + lane];     \
            ffma2(s2[0][k], a0.x, w2.x); ffma2(s2[0][k], a0.y, w2.y);        \
            ffma2(s2[1][k], a1.x, w2.x); ffma2(s2[1][k], a1.y, w2.y);        \
            ffma2(s2[2][k], a2.x, w2.x); ffma2(s2[2][k], a2.y, w2.y);        \
            ffma2(s2[3][k], a3.x, w2.x); ffma2(s2[3][k], a3.y, w2.y);        \
        }                                                                    \
    } while (0)

    // ---- steady state: issue c+3, wait until stage c landed, compute c.
    //      Lane reads only its own copied bytes -> no sync of any kind.
    ISSUE(3); cp_wait<3>(); COMPUTE(0);
    ISSUE(4); cp_wait<3>(); COMPUTE(1);
    ISSUE(5); cp_wait<3>(); COMPUTE(2);
    ISSUE(6); cp_wait<3>(); COMPUTE(3);
    ISSUE(7); cp_wait<3>(); COMPUTE(4);
    cp_wait<2>();           COMPUTE(5);
    cp_wait<1>();           COMPUTE(6);
    cp_wait<0>();           COMPUTE(7);

    // ---- collapse packed pairs, then warp butterfly reduce
    float s[ROWS_PER_WARP][KD];
    #pragma unroll
    for (int r = 0; r < ROWS_PER_WARP; ++r)
        #pragma unroll
        for (int k = 0; k < KD; ++k) s[r][k] = f32x2_sum(s2[r][k]);

    #pragma unroll
    for (int off = 16; off > 0; off >>= 1)
        #pragma unroll
        for (int r = 0; r < ROWS_PER_WARP; ++r)
            #pragma unroll
            for (int k = 0; k < KD; ++k)
                s[r][k] += __shfl_xor_sync(0xffffffffu, s[r][k], off);

    // ---- epilogue: lanes 0..3 each finalize one row
    if (lane < ROWS_PER_WARP) {
        float zs[KD];
        #pragma unroll
        for (int k = 0; k < KD; ++k) {
            zs[k] = (lane == 1) ? s[1][k]
                  : (lane == 2) ? s[2][k]
                  : (lane == 3) ? s[3][k]
                  :               s[0][k];
        }

        float ss = 0.f;
        #pragma unroll
        for (int k = 0; k < KD; ++k) { zs[k] = tanhf(zs[k]); ss += zs[k] * zs[k]; }
        const float invn = 1.f / fmaxf(sqrtf(ss), 1e-6f);

        // softmax of -h*(3 - 3*dot) == softmax of (3*h*invn)*dot
        const float scale = 3.f * smem[SM_H] * invn;
        float lg[NP]; float mx = -1e30f;
        #pragma unroll
        for (int p = 0; p < NP; ++p) {
            float d = 0.f;
            #pragma unroll
            for (int k = 0; k < KD; ++k) d = fmaf(zs[k], p_s[p * 8 + k], d);
            lg[p] = scale * d;
            mx = fmaxf(mx, lg[p]);
        }
        float se = 0.f;
        #pragma unroll
        for (int p = 0; p < NP; ++p) { lg[p] = __expf(lg[p] - mx); se += lg[p]; }
        const float is = 1.f / se;

        const int row = row0 + lane;
        float4* o = reinterpret_cast<float4*>(out + (size_t)row * NP);
        o[0] = make_float4(lg[0] * is, lg[1] * is, lg[2] * is, lg[3] * is);
        o[1] = make_float4(lg[4] * is, lg[5] * is, lg[6] * is, lg[7] * is);
    }
    #undef ISSUE
    #undef COMPUTE
}

extern "C" void kernel_launch(void* const* d_in, const int* in_sizes, int n_in,
                              void* d_out, int out_size)
{
    const float* x      = (const float*)d_in[0];   // (4,8192,1024) f32
    const float* W      = (const float*)d_in[1];   // (6,1024) f32
    const float* protos = (const float*)d_in[2];   // (8,6) f32
    const float* hs     = (const float*)d_in[3];   // scalar f32
    float*       out    = (float*)d_out;           // (4,8192,8) f32

    // opt in to >48KB dynamic smem (attribute set, not an allocation; idempotent)
    cudaFuncSetAttribute(q6_kernel, cudaFuncAttributeMaxDynamicSharedMemorySize, SMEM_BYTES);

    q6_kernel<<<GRID, THREADS, SMEM_BYTES>>>(x, W, protos, hs, out);
}